// round 1
// baseline (speedup 1.0000x reference)
#include <cuda_runtime.h>
#include <math.h>

#define NINST 128
#define CT_   80
#define CS_   53
#define H_    400
#define W_    400
#define HW_   (H_ * W_)
#define MS_   28
#define NCH   (CS_ + NINST)      // 181
#define HG_   1600
#define THREADS 256
#define GRID_ (HW_ / THREADS)    // 625 (exact: 160000 / 256)

static_assert(HW_ % THREADS == 0, "exact grid");

struct InstP {
    int   ylo, xlo, yhi, xhi;   // union coverage box (inclusive), ylo/xlo also bilinear origin
    int   y2m, x2m;             // mask-valid upper bound inclusive: min(y2b, H-1)
    int   cy2, cx2;             // semantic box exclusive upper
    float scy, scx;             // MS / hh, MS / ww
    int   thing_off;            // cls * HW
    int   mask_off;             // (n*CT + cls) * MS*MS
};

__device__ float g_nll[GRID_];
__device__ int   g_cnt[GRID_];

__global__ void __launch_bounds__(THREADS)
pan_fused_kernel(const float* __restrict__ mask_logits,
                 const float* __restrict__ stuff_logit,
                 const float* __restrict__ thing_logit,
                 const float* __restrict__ bbox,
                 const int*   __restrict__ cls_idx,
                 const int*   __restrict__ gt,
                 float* __restrict__ out)
{
    __shared__ InstP sp[NINST];
    __shared__ float red_s[THREADS];
    __shared__ int   red_c[THREADS];

    const int tid = threadIdx.x;

    // ---- per-block instance parameter setup (cheap, L2-broadcast reads) ----
    for (int n = tid; n < NINST; n += THREADS) {
        float x0f = bbox[n * 4 + 0];
        float y0f = bbox[n * 4 + 1];
        float x2f = bbox[n * 4 + 2];
        float y2f = bbox[n * 4 + 3];
        int cls = cls_idx[n];

        // bl = floor(bbox / 4)
        int x0b = (int)floorf(x0f * 0.25f);
        int y0b = (int)floorf(y0f * 0.25f);
        int x2b = (int)floorf(x2f * 0.25f);
        int y2b = (int)floorf(y2f * 0.25f);
        int hh = y2b - y0b + 1;
        int ww = x2b - x0b + 1;

        // semantic box: cy1 = trunc(bf) (== y0b since bbox>=0),
        // cy2 = trunc(rint(bf_hi) + 1)
        int cx2 = (int)(rintf(x2f * 0.25f) + 1.0f);
        int cy2 = (int)(rintf(y2f * 0.25f) + 1.0f);

        InstP q;
        q.ylo = max(y0b, 0);            // bbox >= 0 so == y0b (bilinear origin too)
        q.xlo = max(x0b, 0);
        q.y2m = min(y2b, H_ - 1);
        q.x2m = min(x2b, W_ - 1);
        q.cy2 = cy2;
        q.cx2 = cx2;
        q.yhi = min(max(y2b, cy2 - 1), H_ - 1);
        q.xhi = min(max(x2b, cx2 - 1), W_ - 1);
        q.scy = (float)MS_ / (float)hh;
        q.scx = (float)MS_ / (float)ww;
        q.thing_off = cls * HW_;
        q.mask_off  = (n * CT_ + cls) * (MS_ * MS_);
        sp[n] = q;
    }
    __syncthreads();

    const int p = blockIdx.x * THREADS + tid;   // p < HW_ always (exact grid)
    const int y = p / W_;
    const int x = p - y * W_;

    // downsampled GT: gt[4y, 4x]
    const int g   = gt[(y * 4) * HG_ + (x * 4)];
    const int tgt = min(max(g, 0), NCH - 1);
    const bool valid = (g != 255);
    const int tgt_inst = tgt - CS_;   // >=0 only if target is a thing channel

    float s  = 0.0f;   // sum of exp over all 181 channels (values bounded, no max shift)
    float vt = 0.0f;   // logit at target channel (0 if uncovered thing channel)

    // ---- stuff channels: copy + exp ----
    #pragma unroll 4
    for (int c = 0; c < CS_; ++c) {
        float v = stuff_logit[c * HW_ + p];
        out[c * HW_ + p] = v;
        s += __expf(v);
        if (c == tgt) vt = v;
    }

    // ---- thing channels: bbox-gated bilinear + semantic gather ----
    int nzero = 0;
    for (int n = 0; n < NINST; ++n) {
        InstP q = sp[n];   // uniform across warp -> smem broadcast
        float v = 0.0f;
        if (y >= q.ylo && y <= q.yhi && x >= q.xlo && x <= q.xhi) {
            if (y < q.cy2 && x < q.cx2)
                v += thing_logit[q.thing_off + p];
            if (y <= q.y2m && x <= q.x2m) {
                float sy = ((float)(y - q.ylo) + 0.5f) * q.scy - 0.5f;
                float fy = floorf(sy);
                float ty = sy - fy;
                int iyi = (int)fy;
                int iy0 = min(max(iyi, 0), MS_ - 1);
                int iy1 = min(max(iyi + 1, 0), MS_ - 1);

                float sx = ((float)(x - q.xlo) + 0.5f) * q.scx - 0.5f;
                float fx = floorf(sx);
                float tx = sx - fx;
                int ixi = (int)fx;
                int ix0 = min(max(ixi, 0), MS_ - 1);
                int ix1 = min(max(ixi + 1, 0), MS_ - 1);

                const float* m = mask_logits + q.mask_off;
                float m00 = m[iy0 * MS_ + ix0];
                float m10 = m[iy1 * MS_ + ix0];
                float m01 = m[iy0 * MS_ + ix1];
                float m11 = m[iy1 * MS_ + ix1];
                float c0 = m00 * (1.0f - ty) + m10 * ty;
                float c1 = m01 * (1.0f - ty) + m11 * ty;
                v += c0 * (1.0f - tx) + c1 * tx;
            }
            s += __expf(v);
        } else {
            nzero++;       // exp(0) == 1, summed in bulk below
        }
        out[(CS_ + n) * HW_ + p] = v;
        if (n == tgt_inst) vt = v;
    }
    s += (float)nzero;

    float nll = valid ? (logf(s) - vt) : 0.0f;

    // ---- deterministic per-block reduction ----
    red_s[tid] = nll;
    red_c[tid] = valid ? 1 : 0;
    __syncthreads();
    for (int off = THREADS / 2; off > 0; off >>= 1) {
        if (tid < off) {
            red_s[tid] += red_s[tid + off];
            red_c[tid] += red_c[tid + off];
        }
        __syncthreads();
    }
    if (tid == 0) {
        g_nll[blockIdx.x] = red_s[0];
        g_cnt[blockIdx.x] = red_c[0];
    }
}

__global__ void loss_reduce_kernel(float* __restrict__ out, int out_size)
{
    __shared__ float rs[256];
    __shared__ int   rc[256];
    int t = threadIdx.x;
    float s = 0.0f;
    int   c = 0;
    for (int i = t; i < GRID_; i += 256) {   // fixed order -> deterministic
        s += g_nll[i];
        c += g_cnt[i];
    }
    rs[t] = s;
    rc[t] = c;
    __syncthreads();
    for (int off = 128; off > 0; off >>= 1) {
        if (t < off) { rs[t] += rs[t + off]; rc[t] += rc[t + off]; }
        __syncthreads();
    }
    if (t == 0) {
        float denom = fmaxf((float)rc[0], 1.0f);
        out[out_size - 1] = rs[0] / denom;   // LOSS_W = 1.0
    }
}

extern "C" void kernel_launch(void* const* d_in, const int* in_sizes, int n_in,
                              void* d_out, int out_size)
{
    const float* mask_logits = (const float*)d_in[0];
    const float* stuff_logit = (const float*)d_in[1];
    const float* thing_logit = (const float*)d_in[2];
    const float* bbox        = (const float*)d_in[3];
    const int*   cls_idx     = (const int*)d_in[4];
    const int*   gt          = (const int*)d_in[5];
    float* out = (float*)d_out;

    pan_fused_kernel<<<GRID_, THREADS>>>(mask_logits, stuff_logit, thing_logit,
                                         bbox, cls_idx, gt, out);
    loss_reduce_kernel<<<1, 256>>>(out, out_size);
}